// round 16
// baseline (speedup 1.0000x reference)
#include <cuda_runtime.h>
#include <cuda_fp16.h>
#include <cstdint>

#define N_ROWS 100000
#define IN_CH  256
#define OUT_CH 128
#define KVOL   8

#define BM 128
#define BK 32
#define NCHUNK 8                 // IN_CH / BK
#define MTILES 782               // ceil(100000/128)
#define NIT 4                    // iterations of K=64 (two chunks each)

// fragment-packed chunk tiles, half2 units (uint32)
#define CH_U32 2048              // one BK=32 chunk
#define CH2_U32 4096             // one K=64 iteration tile (A or B)
#define NBUF 3
#define SM_U32 (2 * NBUF * CH2_U32)   // A0..A2 | B0..B2 = 96KB

// fused prep block ranges
#define BLK_AT (MTILES * 4)      // 3128 blocks: tile = b>>2, chunk-pair = b&3
#define BLK_WT 512               // 8*8*2048/256

__device__ __align__(16) uint32_t g_At[MTILES * NCHUNK * CH_U32];   // 51.25MB
__device__ __align__(16) uint32_t g_Wt[KVOL * NCHUNK * CH_U32];     // 512KB

__device__ __forceinline__ uint32_t pack_h2(float a, float b) {
    __half2 h = __floats2half2_rn(a, b);
    return *reinterpret_cast<uint32_t*>(&h);
}
__device__ __forceinline__ uint32_t smem_u32(const void* p) {
    uint32_t a;
    asm("{ .reg .u64 t; cvta.to.shared.u64 t, %1; cvt.u32.u64 %0, t; }" : "=r"(a) : "l"(p));
    return a;
}
__device__ __forceinline__ int aIdx(int ks, int m16, int g, int l4, int reg) {
    return (((ks * 8 + m16) * 8 + g) * 4 + l4) * 4 + reg;
}

// ---------------------------------------------------------------------------
// fused prep: blocks [0,3128) pack A (2 chunks each); [3128,3640) pack W.
// A-pack: each thread owns one 16-k segment of a row-pair -> full uint4
// fragments, 64B contiguous stores per thread (100% sector utilization).
__global__ __launch_bounds__(256)
void prep_all(const float* __restrict__ A, const float* __restrict__ W)
{
    const int b = blockIdx.x;
    const int tid = threadIdx.x;

    if (b < BLK_AT) {
        const int tile = b >> 2;
        const int cpair = b & 3;
        const int m0 = tile * BM;
        const int ci   = tid >> 7;           // which chunk of the pair
        const int ks   = (tid >> 6) & 1;     // 16-k segment within chunk
        const int pr   = tid & 63;
        const int sm16 = pr >> 3;
        const int sg   = pr & 7;
        const int c    = cpair * 2 + ci;
        const int r0   = m0 + sm16 * 16 + sg;
        const int r1   = r0 + 8;
        const int k0   = c * BK + ks * 16;
        uint32_t* dst = g_At + (size_t)tile * NCHUNK * CH_U32 + c * CH_U32;

        float v0[16], v1[16];
        #pragma unroll
        for (int i = 0; i < 16; ++i) { v0[i] = 0.f; v1[i] = 0.f; }
        if (r0 < N_ROWS) {
            const float4* p = (const float4*)(A + (size_t)r0 * IN_CH + k0);
            *(float4*)(v0) = p[0]; *(float4*)(v0+4) = p[1];
            *(float4*)(v0+8) = p[2]; *(float4*)(v0+12) = p[3];
        }
        if (r1 < N_ROWS) {
            const float4* p = (const float4*)(A + (size_t)r1 * IN_CH + k0);
            *(float4*)(v1) = p[0]; *(float4*)(v1+4) = p[1];
            *(float4*)(v1+8) = p[2]; *(float4*)(v1+12) = p[3];
        }
        #pragma unroll
        for (int l4 = 0; l4 < 4; ++l4) {
            uint4 q;
            q.x = pack_h2(v0[l4*2],     v0[l4*2 + 1]);      // r0 @ k lo
            q.y = pack_h2(v1[l4*2],     v1[l4*2 + 1]);      // r1 @ k lo
            q.z = pack_h2(v0[8 + l4*2], v0[8 + l4*2 + 1]);  // r0 @ k+8
            q.w = pack_h2(v1[8 + l4*2], v1[8 + l4*2 + 1]);  // r1 @ k+8
            *(uint4*)(dst + aIdx(ks, sm16, sg, l4, 0)) = q;
        }
    } else {
        // ---- pack W (round-5 proven mapping) ----
        int d = (b - BLK_AT) * 256 + tid;    // 0 .. 8*8*2048-1
        int kb = d >> 14;
        int c  = (d >> 11) & 7;
        int r  = d & 2047;
        int j   = r & 1;
        int l4  = (r >> 1) & 3;
        int col = (r >> 3) & 127;
        int ks  = r >> 10;
        int k0 = c * BK + ks * 16 + j * 8 + l4 * 2;
        float w0 = W[((size_t)kb * IN_CH + k0) * OUT_CH + col];
        float w1 = W[((size_t)kb * IN_CH + k0 + 1) * OUT_CH + col];
        g_Wt[d] = pack_h2(w0, w1);
    }
}

// ---------------------------------------------------------------------------
// 4 warps, 64x64 warp tiles. K=64 per barrier, triple-buffered smem tiles
// (distance-2 prefetch, wait_group 1), ks-level operand double-buffering.
// kb==0 CTAs also emit coords in the epilogue.  (round-15 proven, unchanged)
__global__ __launch_bounds__(128, 2)
void gemm_fp16(float* __restrict__ out,
               const int* __restrict__ coords,
               float* __restrict__ outc,
               int do_coords)
{
    extern __shared__ uint32_t smem[];   // [A0|A1|A2|B0|B1|B2] x 4096 u32

    const int tid  = threadIdx.x;
    const int kb   = blockIdx.x;
    const int tile = blockIdx.y;
    const int m0   = tile * BM;
    const int lane = tid & 31;
    const int wid  = tid >> 5;
    const int wm   = (wid >> 1) * 64;
    const int wn   = (wid & 1) * 64;
    const int m16b = wm >> 4;
    const int g    = lane >> 2;
    const int l4   = lane & 3;

    const uint32_t sA = smem_u32(smem);
    const uint32_t sB = sA + NBUF * CH2_U32 * 4;

    auto cpPair = [&](int it, int buf) {    // copies chunks 2*it, 2*it+1
        const uint32_t* srcA = g_At + ((size_t)tile * NCHUNK + it * 2) * CH_U32;
        const uint32_t* srcB = g_Wt + ((size_t)kb * NCHUNK + it * 2) * CH_U32;
        uint32_t dA = sA + (buf * CH2_U32 + tid * 4) * 4;
        uint32_t dB = sB + (buf * CH2_U32 + tid * 4) * 4;
        #pragma unroll
        for (int i = 0; i < 8; ++i) {
            asm volatile("cp.async.cg.shared.global [%0], [%1], 16;"
                         :: "r"(dA + i * 2048), "l"(srcA + tid * 4 + i * 512) : "memory");
            asm volatile("cp.async.cg.shared.global [%0], [%1], 16;"
                         :: "r"(dB + i * 2048), "l"(srcB + tid * 4 + i * 512) : "memory");
        }
        asm volatile("cp.async.commit_group;" ::: "memory");
    };

    float acc[4][8][4];
    #pragma unroll
    for (int mt = 0; mt < 4; ++mt)
        #pragma unroll
        for (int nt = 0; nt < 8; ++nt)
            #pragma unroll
            for (int i = 0; i < 4; ++i) acc[mt][nt][i] = 0.f;

    cpPair(0, 0);
    cpPair(1, 1);

    #pragma unroll 1
    for (int it = 0; it < NIT; ++it) {
        const int buf = it % NBUF;
        if (it < NIT - 1) asm volatile("cp.async.wait_group 1;" ::: "memory");
        else              asm volatile("cp.async.wait_group 0;" ::: "memory");
        __syncthreads();   // compute(it-1) done by all; copies of `it` visible
        if (it + 2 < NIT) cpPair(it + 2, (it + 2) % NBUF);

        const uint32_t* Ab = smem + buf * CH2_U32;
        const uint32_t* Bb = smem + (NBUF + buf) * CH2_U32;

        // operand double-buffer across the 4 k-slices of this K=64 tile
        uint4 ar[2][4];
        uint2 br[2][8];
        auto ldOps = [&](int ks4, int pb) {
            const uint32_t* Ac = Ab + (ks4 >> 1) * CH_U32;
            const uint32_t* Bc = Bb + (ks4 >> 1) * CH_U32;
            const int ksi = ks4 & 1;
            #pragma unroll
            for (int mt = 0; mt < 4; ++mt)
                ar[pb][mt] = *(const uint4*)(Ac + aIdx(ksi, m16b + mt, g, l4, 0));
            #pragma unroll
            for (int nt = 0; nt < 8; ++nt)
                br[pb][nt] = *(const uint2*)(Bc + ((ksi * 128 + wn + nt * 8 + g) * 4 + l4) * 2);
        };

        ldOps(0, 0);
        #pragma unroll
        for (int ks4 = 0; ks4 < 4; ++ks4) {
            const int pb = ks4 & 1;
            if (ks4 + 1 < 4) ldOps(ks4 + 1, pb ^ 1);   // LDS in flight under MMAs
            #pragma unroll
            for (int nt = 0; nt < 8; ++nt) {
                #pragma unroll
                for (int mt = 0; mt < 4; ++mt) {
                    asm volatile(
                        "mma.sync.aligned.m16n8k16.row.col.f32.f16.f16.f32 "
                        "{%0,%1,%2,%3}, {%4,%5,%6,%7}, {%8,%9}, {%0,%1,%2,%3};\n"
                        : "+f"(acc[mt][nt][0]), "+f"(acc[mt][nt][1]),
                          "+f"(acc[mt][nt][2]), "+f"(acc[mt][nt][3])
                        : "r"(ar[pb][mt].x), "r"(ar[pb][mt].y),
                          "r"(ar[pb][mt].z), "r"(ar[pb][mt].w),
                          "r"(br[pb][nt].x), "r"(br[pb][nt].y));
                }
            }
        }
    }

    // epilogue: out[(n*8 + kb)*128 + col]
    #pragma unroll
    for (int mt = 0; mt < 4; ++mt) {
        const int r0 = m0 + wm + mt * 16 + g;
        const int r1 = r0 + 8;
        #pragma unroll
        for (int nt = 0; nt < 8; ++nt) {
            const int col = wn + nt * 8 + l4 * 2;
            if (r0 < N_ROWS) {
                *(float2*)(out + ((size_t)r0 * KVOL + kb) * OUT_CH + col) =
                    make_float2(acc[mt][nt][0], acc[mt][nt][1]);
            }
            if (r1 < N_ROWS) {
                *(float2*)(out + ((size_t)r1 * KVOL + kb) * OUT_CH + col) =
                    make_float2(acc[mt][nt][2], acc[mt][nt][3]);
            }
        }
    }

    // coords for this tile's 128 rows (kb==0 CTAs only), 1 row per thread
    if (do_coords && kb == 0) {
        const int n = m0 + tid;
        if (n < N_ROWS) {
            float cx = (float)(2 * __ldg(coords + n * 3 + 0));
            float cy = (float)(2 * __ldg(coords + n * 3 + 1));
            float cz = (float)(2 * __ldg(coords + n * 3 + 2));
            float4 v[6];
            float* vf = (float*)v;
            #pragma unroll
            for (int k = 0; k < 8; ++k) {
                vf[k * 3 + 0] = cx + (float)((k >> 2) & 1);
                vf[k * 3 + 1] = cy + (float)((k >> 1) & 1);
                vf[k * 3 + 2] = cz + (float)(k & 1);
            }
            float4* dst = (float4*)(outc + (size_t)n * 24);
            #pragma unroll
            for (int i = 0; i < 6; ++i) dst[i] = v[i];
        }
    }
}

// ---------------------------------------------------------------------------
extern "C" void kernel_launch(void* const* d_in, const int* in_sizes, int n_in,
                              void* d_out, int out_size)
{
    const float* feats  = nullptr;
    const int*   coords = nullptr;
    const float* W      = nullptr;
    for (int i = 0; i < n_in; ++i) {
        if      (in_sizes[i] == N_ROWS * IN_CH)        feats  = (const float*)d_in[i];
        else if (in_sizes[i] == N_ROWS * 3)            coords = (const int*)d_in[i];
        else if (in_sizes[i] == KVOL * IN_CH * OUT_CH) W      = (const float*)d_in[i];
    }
    float* out = (float*)d_out;

    cudaFuncSetAttribute(gemm_fp16,
                         cudaFuncAttributeMaxDynamicSharedMemorySize, SM_U32 * 4);

    prep_all<<<BLK_AT + BLK_WT, 256>>>(feats, W);

    const long long featsN = (long long)N_ROWS * KVOL * OUT_CH;
    const long long coordN = (long long)N_ROWS * KVOL * 3;
    const int want_coords =
        ((long long)out_size >= featsN + coordN && coords != nullptr) ? 1 : 0;

    dim3 grid(KVOL, MTILES);   // kb fastest: 8 CTAs share each A tile in L2
    gemm_fp16<<<grid, 128, SM_U32 * 4>>>(out, coords, out + featsN, want_coords);
}

// round 17
// speedup vs baseline: 1.0254x; 1.0254x over previous
#include <cuda_runtime.h>
#include <cuda_fp16.h>
#include <cstdint>

#define N_ROWS 100000
#define IN_CH  256
#define OUT_CH 128
#define KVOL   8

#define BM 128
#define BK 32
#define NCHUNK 8                 // IN_CH / BK
#define MTILES 782               // ceil(100000/128)
#define NIT 4                    // iterations of K=64 (two chunks each)

// fragment-packed chunk tiles, half2 units (uint32)
#define CH_U32 2048              // one BK=32 chunk
#define CH2_U32 4096             // one K=64 iteration tile (A or B)
#define NBUF 3
#define SM_U32 (2 * NBUF * CH2_U32)   // A0..A2 | B0..B2 = 96KB

// fused prep block ranges
#define BLK_AT (MTILES * 4)      // 3128 blocks: tile = b>>2, chunk-pair = b&3
#define BLK_WT 512               // 8*8*2048/256

__device__ __align__(16) uint32_t g_At[MTILES * NCHUNK * CH_U32];   // 51.25MB
__device__ __align__(16) uint32_t g_Wt[KVOL * NCHUNK * CH_U32];     // 512KB

__device__ __forceinline__ uint32_t pack_h2(float a, float b) {
    __half2 h = __floats2half2_rn(a, b);
    return *reinterpret_cast<uint32_t*>(&h);
}
__device__ __forceinline__ uint32_t smem_u32(const void* p) {
    uint32_t a;
    asm("{ .reg .u64 t; cvta.to.shared.u64 t, %1; cvt.u32.u64 %0, t; }" : "=r"(a) : "l"(p));
    return a;
}
__device__ __forceinline__ int aIdx(int ks, int m16, int g, int l4, int reg) {
    return (((ks * 8 + m16) * 8 + g) * 4 + l4) * 4 + reg;
}

// ---------------------------------------------------------------------------
// fused prep: blocks [0,3128) pack A (2 chunks each); [3128,3640) pack W.
// (round-15 proven version)
__global__ __launch_bounds__(256)
void prep_all(const float* __restrict__ A, const float* __restrict__ W)
{
    const int b = blockIdx.x;
    const int tid = threadIdx.x;

    if (b < BLK_AT) {
        // ---- pack A: tile = b>>2, chunk-pair = b&3 ----
        const int tile = b >> 2;
        const int cpair = b & 3;
        const int m0 = tile * BM;
        const int pr = tid >> 2;
        const int sm16 = pr >> 3;
        const int sg = pr & 7;
        const int kseg = (tid & 3) * 8;
        const int ks = kseg >> 4;
        const int hi = (kseg >> 3) & 1;
        const int r0 = m0 + sm16 * 16 + sg;
        const int r1 = r0 + 8;
        uint32_t* dst = g_At + (size_t)tile * NCHUNK * CH_U32;

        #pragma unroll
        for (int ci = 0; ci < 2; ++ci) {
            const int c = cpair * 2 + ci;
            const int k0 = c * BK + kseg;
            float v0[8] = {0,0,0,0,0,0,0,0}, v1[8] = {0,0,0,0,0,0,0,0};
            if (r0 < N_ROWS) {
                *(float4*)(v0)     = *(const float4*)(A + (size_t)r0 * IN_CH + k0);
                *(float4*)(v0 + 4) = *(const float4*)(A + (size_t)r0 * IN_CH + k0 + 4);
            }
            if (r1 < N_ROWS) {
                *(float4*)(v1)     = *(const float4*)(A + (size_t)r1 * IN_CH + k0);
                *(float4*)(v1 + 4) = *(const float4*)(A + (size_t)r1 * IN_CH + k0 + 4);
            }
            #pragma unroll
            for (int l4 = 0; l4 < 4; ++l4) {
                uint2 p;
                p.x = pack_h2(v0[l4 * 2], v0[l4 * 2 + 1]);
                p.y = pack_h2(v1[l4 * 2], v1[l4 * 2 + 1]);
                *(uint2*)(dst + c * CH_U32 + aIdx(ks, sm16, sg, l4, hi * 2)) = p;
            }
        }
    } else {
        // ---- pack W (round-5 proven mapping) ----
        int d = (b - BLK_AT) * 256 + tid;    // 0 .. 8*8*2048-1
        int kb = d >> 14;
        int c  = (d >> 11) & 7;
        int r  = d & 2047;
        int j   = r & 1;
        int l4  = (r >> 1) & 3;
        int col = (r >> 3) & 127;
        int ks  = r >> 10;
        int k0 = c * BK + ks * 16 + j * 8 + l4 * 2;
        float w0 = W[((size_t)kb * IN_CH + k0) * OUT_CH + col];
        float w1 = W[((size_t)kb * IN_CH + k0 + 1) * OUT_CH + col];
        g_Wt[d] = pack_h2(w0, w1);
    }
}

// ---------------------------------------------------------------------------
// 4 warps, 64x64 warp tiles. K=64 per barrier, triple-buffered smem tiles
// (distance-2 prefetch, wait_group 1), ks-level operand double-buffering.
// kb==0 CTAs also emit coords in the epilogue.  (round-15 proven, unchanged)
__global__ __launch_bounds__(128, 2)
void gemm_fp16(float* __restrict__ out,
               const int* __restrict__ coords,
               float* __restrict__ outc,
               int do_coords)
{
    extern __shared__ uint32_t smem[];   // [A0|A1|A2|B0|B1|B2] x 4096 u32

    const int tid  = threadIdx.x;
    const int kb   = blockIdx.x;
    const int tile = blockIdx.y;
    const int m0   = tile * BM;
    const int lane = tid & 31;
    const int wid  = tid >> 5;
    const int wm   = (wid >> 1) * 64;
    const int wn   = (wid & 1) * 64;
    const int m16b = wm >> 4;
    const int g    = lane >> 2;
    const int l4   = lane & 3;

    const uint32_t sA = smem_u32(smem);
    const uint32_t sB = sA + NBUF * CH2_U32 * 4;

    auto cpPair = [&](int it, int buf) {    // copies chunks 2*it, 2*it+1
        const uint32_t* srcA = g_At + ((size_t)tile * NCHUNK + it * 2) * CH_U32;
        const uint32_t* srcB = g_Wt + ((size_t)kb * NCHUNK + it * 2) * CH_U32;
        uint32_t dA = sA + (buf * CH2_U32 + tid * 4) * 4;
        uint32_t dB = sB + (buf * CH2_U32 + tid * 4) * 4;
        #pragma unroll
        for (int i = 0; i < 8; ++i) {
            asm volatile("cp.async.cg.shared.global [%0], [%1], 16;"
                         :: "r"(dA + i * 2048), "l"(srcA + tid * 4 + i * 512) : "memory");
            asm volatile("cp.async.cg.shared.global [%0], [%1], 16;"
                         :: "r"(dB + i * 2048), "l"(srcB + tid * 4 + i * 512) : "memory");
        }
        asm volatile("cp.async.commit_group;" ::: "memory");
    };

    float acc[4][8][4];
    #pragma unroll
    for (int mt = 0; mt < 4; ++mt)
        #pragma unroll
        for (int nt = 0; nt < 8; ++nt)
            #pragma unroll
            for (int i = 0; i < 4; ++i) acc[mt][nt][i] = 0.f;

    cpPair(0, 0);
    cpPair(1, 1);

    #pragma unroll 1
    for (int it = 0; it < NIT; ++it) {
        const int buf = it % NBUF;
        if (it < NIT - 1) asm volatile("cp.async.wait_group 1;" ::: "memory");
        else              asm volatile("cp.async.wait_group 0;" ::: "memory");
        __syncthreads();   // compute(it-1) done by all; copies of `it` visible
        if (it + 2 < NIT) cpPair(it + 2, (it + 2) % NBUF);

        const uint32_t* Ab = smem + buf * CH2_U32;
        const uint32_t* Bb = smem + (NBUF + buf) * CH2_U32;

        // operand double-buffer across the 4 k-slices of this K=64 tile
        uint4 ar[2][4];
        uint2 br[2][8];
        auto ldOps = [&](int ks4, int pb) {
            const uint32_t* Ac = Ab + (ks4 >> 1) * CH_U32;
            const uint32_t* Bc = Bb + (ks4 >> 1) * CH_U32;
            const int ksi = ks4 & 1;
            #pragma unroll
            for (int mt = 0; mt < 4; ++mt)
                ar[pb][mt] = *(const uint4*)(Ac + aIdx(ksi, m16b + mt, g, l4, 0));
            #pragma unroll
            for (int nt = 0; nt < 8; ++nt)
                br[pb][nt] = *(const uint2*)(Bc + ((ksi * 128 + wn + nt * 8 + g) * 4 + l4) * 2);
        };

        ldOps(0, 0);
        #pragma unroll
        for (int ks4 = 0; ks4 < 4; ++ks4) {
            const int pb = ks4 & 1;
            if (ks4 + 1 < 4) ldOps(ks4 + 1, pb ^ 1);   // LDS in flight under MMAs
            #pragma unroll
            for (int nt = 0; nt < 8; ++nt) {
                #pragma unroll
                for (int mt = 0; mt < 4; ++mt) {
                    asm volatile(
                        "mma.sync.aligned.m16n8k16.row.col.f32.f16.f16.f32 "
                        "{%0,%1,%2,%3}, {%4,%5,%6,%7}, {%8,%9}, {%0,%1,%2,%3};\n"
                        : "+f"(acc[mt][nt][0]), "+f"(acc[mt][nt][1]),
                          "+f"(acc[mt][nt][2]), "+f"(acc[mt][nt][3])
                        : "r"(ar[pb][mt].x), "r"(ar[pb][mt].y),
                          "r"(ar[pb][mt].z), "r"(ar[pb][mt].w),
                          "r"(br[pb][nt].x), "r"(br[pb][nt].y));
                }
            }
        }
    }

    // epilogue: out[(n*8 + kb)*128 + col]
    #pragma unroll
    for (int mt = 0; mt < 4; ++mt) {
        const int r0 = m0 + wm + mt * 16 + g;
        const int r1 = r0 + 8;
        #pragma unroll
        for (int nt = 0; nt < 8; ++nt) {
            const int col = wn + nt * 8 + l4 * 2;
            if (r0 < N_ROWS) {
                *(float2*)(out + ((size_t)r0 * KVOL + kb) * OUT_CH + col) =
                    make_float2(acc[mt][nt][0], acc[mt][nt][1]);
            }
            if (r1 < N_ROWS) {
                *(float2*)(out + ((size_t)r1 * KVOL + kb) * OUT_CH + col) =
                    make_float2(acc[mt][nt][2], acc[mt][nt][3]);
            }
        }
    }

    // coords for this tile's 128 rows (kb==0 CTAs only), 1 row per thread
    if (do_coords && kb == 0) {
        const int n = m0 + tid;
        if (n < N_ROWS) {
            float cx = (float)(2 * __ldg(coords + n * 3 + 0));
            float cy = (float)(2 * __ldg(coords + n * 3 + 1));
            float cz = (float)(2 * __ldg(coords + n * 3 + 2));
            float4 v[6];
            float* vf = (float*)v;
            #pragma unroll
            for (int k = 0; k < 8; ++k) {
                vf[k * 3 + 0] = cx + (float)((k >> 2) & 1);
                vf[k * 3 + 1] = cy + (float)((k >> 1) & 1);
                vf[k * 3 + 2] = cz + (float)(k & 1);
            }
            float4* dst = (float4*)(outc + (size_t)n * 24);
            #pragma unroll
            for (int i = 0; i < 6; ++i) dst[i] = v[i];
        }
    }
}

// ---------------------------------------------------------------------------
extern "C" void kernel_launch(void* const* d_in, const int* in_sizes, int n_in,
                              void* d_out, int out_size)
{
    const float* feats  = nullptr;
    const int*   coords = nullptr;
    const float* W      = nullptr;
    for (int i = 0; i < n_in; ++i) {
        if      (in_sizes[i] == N_ROWS * IN_CH)        feats  = (const float*)d_in[i];
        else if (in_sizes[i] == N_ROWS * 3)            coords = (const int*)d_in[i];
        else if (in_sizes[i] == KVOL * IN_CH * OUT_CH) W      = (const float*)d_in[i];
    }
    float* out = (float*)d_out;

    cudaFuncSetAttribute(gemm_fp16,
                         cudaFuncAttributeMaxDynamicSharedMemorySize, SM_U32 * 4);

    prep_all<<<BLK_AT + BLK_WT, 256>>>(feats, W);

    const long long featsN = (long long)N_ROWS * KVOL * OUT_CH;
    const long long coordN = (long long)N_ROWS * KVOL * 3;
    const int want_coords =
        ((long long)out_size >= featsN + coordN && coords != nullptr) ? 1 : 0;

    dim3 grid(KVOL, MTILES);   // kb fastest: 8 CTAs share each A tile in L2
    gemm_fp16<<<grid, 128, SM_U32 * 4>>>(out, coords, out + featsN, want_coords);
}